// round 17
// baseline (speedup 1.0000x reference)
#include <cuda_runtime.h>
typedef unsigned long long ull;

constexpr int Bn = 8, Sn = 2048, Pn = 1024, ITERS = 50;
constexpr int CPB = 32, GRID = Bn * CPB, NT = 256, NW = 8;
constexpr int PH = 16;                         // clamped-phase iterations

constexpr float SQI   = 12.011224081528898f;   // sqrt((1/eps)*log2 e)
constexpr float IL2   = 144.26950408889634f;
constexpr float LOG2S = 11.0f;
constexpr float CL    = 110.f;                 // clamp headroom

__device__ __align__(16) float g_gs[Bn * Pn];  // Qy-form gs
__device__ float g_pp[Bn * Pn * CPB];          // per-column partials [b][j][cta]
__device__ float g_part[GRID];
__device__ unsigned g_cnt[Bn];
__device__ unsigned g_sns[Bn];
__device__ unsigned g_gcnt;

__device__ __forceinline__ float ex2(float x) { float r; asm("ex2.approx.f32 %0, %1;" : "=f"(r) : "f"(x)); return r; }
__device__ __forceinline__ float lg2(float x) { float r; asm("lg2.approx.f32 %0, %1;" : "=f"(r) : "f"(x)); return r; }
__device__ __forceinline__ ull pk(float lo, float hi) { ull r; asm("mov.b64 %0, {%1, %2};" : "=l"(r) : "f"(lo), "f"(hi)); return r; }
__device__ __forceinline__ void upk(ull p, float& a, float& b) { asm("mov.b64 {%0, %1}, %2;" : "=f"(a), "=f"(b) : "l"(p)); }
__device__ __forceinline__ ull add2(ull a, ull b) { ull r; asm("add.rn.f32x2 %0, %1, %2;" : "=l"(r) : "l"(a), "l"(b)); return r; }
__device__ __forceinline__ ull fma2(ull a, ull b, ull c) { ull r; asm("fma.rn.f32x2 %0, %1, %2, %3;" : "=l"(r) : "l"(a), "l"(b), "l"(c)); return r; }
__device__ __forceinline__ float warp_sum(float a) {
    #pragma unroll
    for (int o = 16; o; o >>= 1) a += __shfl_xor_sync(0xffffffffu, a, o);
    return a;
}

// per-batch barrier: release arrive + acquire spin (all CTAs co-resident)
__device__ __forceinline__ void bat_bar(int b, unsigned& ls) {
    ls ^= 1u;
    __syncthreads();
    if (threadIdx.x == 0) {
        unsigned old;
        asm volatile("atom.acq_rel.gpu.add.u32 %0,[%1],%2;"
                     : "=r"(old) : "l"(&g_cnt[b]), "r"(1u) : "memory");
        if (old == CPB - 1) {
            g_cnt[b] = 0;
            asm volatile("st.release.gpu.u32 [%0],%1;" :: "l"(&g_sns[b]), "r"(ls) : "memory");
        } else {
            unsigned v;
            do { asm volatile("ld.acquire.gpu.u32 %0,[%1];" : "=r"(v) : "l"(&g_sns[b]) : "memory"); }
            while (v != ls);
        }
    }
    __syncthreads();
}

__global__ void __launch_bounds__(NT, 2) sinkhorn_kernel(
    const float* __restrict__ pred, const int* __restrict__ labels,
    const float* __restrict__ pos, float* __restrict__ out)
{
    __shared__ __align__(16) float X1L[64], X2L[64], QxL[64];
    __shared__ __align__(16) float Y1c[Pn], Y2c[Pn], Qyc[Pn], l2bC[Pn], RgA[Pn];
    __shared__ float sA[NW * 64], sRf[64], sred[NW];
    __shared__ int swp[8], sPvA[1];

    int tid = threadIdx.x, w = tid >> 5, lane = tid & 31;
    int b = blockIdx.x >> 5, cb = blockIdx.x & 31;
    int row0 = cb * 64, col0 = cb * 32;

    const float2* pr2 = (const float2*)pred + b * Sn;
    const float2* po2 = (const float2*)pos + b * Pn;
    const int*    lab = labels + b * Sn;

    // ---- stage own 64 X rows (prescaled by 2*SQI) ----
    if (tid < 64) {
        float2 p = pr2[row0 + tid];
        X1L[tid] = 2.f * SQI * p.x;  X2L[tid] = 2.f * SQI * p.y;
    }
    // ---- histogram (overlay in RgA region) ----
    int* hist = (int*)RgA;
    for (int i = tid; i < Pn; i += NT) hist[i] = 0;
    __syncthreads();
    for (int s = tid; s < Sn; s += NT) atomicAdd(&hist[lab[s]], 1);
    __syncthreads();
    // ---- compact nonzero-weight positions ----
    int c4[4], tsum = 0;
    #pragma unroll
    for (int k = 0; k < 4; k++) { c4[k] = hist[tid * 4 + k] > 0; tsum += c4[k]; }
    int pre = tsum;
    #pragma unroll
    for (int o = 1; o < 32; o <<= 1) { int v = __shfl_up_sync(~0u, pre, o); if (lane >= o) pre += v; }
    if (lane == 31) swp[w] = pre;
    __syncthreads();
    if (tid == 0) { int r = 0; for (int i = 0; i < 8; i++) { int v = swp[i]; swp[i] = r; r += v; } sPvA[0] = r; }
    __syncthreads();
    int Pv = sPvA[0];
    int off = swp[w] + pre - tsum;
    #pragma unroll
    for (int k = 0; k < 4; k++) {
        if (c4[k]) {
            int p = tid * 4 + k;
            float2 yy = po2[p];
            Y1c[off] = SQI * yy.x;  Y2c[off] = SQI * yy.y;
            l2bC[off] = lg2((float)hist[p] * (1.f / (float)Sn));
            off++;
        }
    }
    __syncthreads();   // hist done; RgA region free
    int PvPad = (Pv + 15) & ~15;
    int nch = PvPad >> 4;              // f-half 16-col chunks
    int ncp = (PvPad + 63) >> 6;       // g-pass 64-col units
    for (int i = tid; i < Pn; i += NT) {
        if (i < Pv) Qyc[i] = -(Y1c[i] * Y1c[i] + Y2c[i] * Y2c[i]);   // g=0 -> Qy=-yn
        else { Qyc[i] = -1e30f; Y1c[i] = 0.f; Y2c[i] = 0.f; l2bC[i] = 0.f; }
    }
    unsigned ls = g_sns[b];
    __syncthreads();

    // per-lane f constants (2 rows/lane)
    float X1a = X1L[lane], X2a = X2L[lane], X1b_ = X1L[lane + 32], X2b_ = X2L[lane + 32];
    ull X1A = pk(X1a, X1a), X2A = pk(X2a, X2a);
    ull X1B = pk(X1b_, X1b_), X2B = pk(X2b_, X2b_);

    for (int it = 0; it < ITERS; ++it) {
        // ================= f half: 64 rows (2/lane), 8 warps stride chunks ====
        if (it == 0) {   // seed Rf = exact row max (fma-only pass)
            float m0 = -3e38f, m1 = -3e38f;
            for (int c = w; c < nch; c += NW) {
                const ulonglong2* y1 = (const ulonglong2*)(Y1c + c * 16);
                const ulonglong2* y2 = (const ulonglong2*)(Y2c + c * 16);
                const ulonglong2* qq = (const ulonglong2*)(Qyc + c * 16);
                #pragma unroll
                for (int j = 0; j < 4; j++) {
                    ulonglong2 ly1 = y1[j], ly2 = y2[j], q = qq[j];
                    ull t; float a, b2;
                    t = fma2(X1A, ly1.x, fma2(X2A, ly2.x, q.x));
                    upk(t, a, b2); m0 = fmaxf(m0, fmaxf(a, b2));
                    t = fma2(X1A, ly1.y, fma2(X2A, ly2.y, q.y));
                    upk(t, a, b2); m0 = fmaxf(m0, fmaxf(a, b2));
                    t = fma2(X1B, ly1.x, fma2(X2B, ly2.x, q.x));
                    upk(t, a, b2); m1 = fmaxf(m1, fmaxf(a, b2));
                    t = fma2(X1B, ly1.y, fma2(X2B, ly2.y, q.y));
                    upk(t, a, b2); m1 = fmaxf(m1, fmaxf(a, b2));
                }
            }
            sA[w * 64 + lane] = m0;  sA[w * 64 + lane + 32] = m1;
            __syncthreads();
            if (tid < 64) {
                float M = -3e38f;
                #pragma unroll
                for (int i = 0; i < NW; i++) M = fmaxf(M, sA[i * 64 + tid]);
                sRf[tid] = M;
            }
            __syncthreads();
        }
        {
            float R0 = sRf[lane], R1 = sRf[lane + 32];
            ull nR0 = pk(-R0, -R0), nR1 = pk(-R1, -R1);
            float a0 = 0.f, a1 = 0.f, a2 = 0.f, a3 = 0.f;
            if (it < PH) {
                for (int c = w; c < nch; c += NW) {
                    const ulonglong2* y1 = (const ulonglong2*)(Y1c + c * 16);
                    const ulonglong2* y2 = (const ulonglong2*)(Y2c + c * 16);
                    const ulonglong2* qq = (const ulonglong2*)(Qyc + c * 16);
                    #pragma unroll
                    for (int j = 0; j < 4; j++) {
                        ulonglong2 ly1 = y1[j], ly2 = y2[j], q = qq[j];
                        ull t; float ta, tb;
                        t = add2(fma2(X1A, ly1.x, fma2(X2A, ly2.x, q.x)), nR0);
                        upk(t, ta, tb);
                        a0 += ex2(fminf(ta, CL)); a1 += ex2(fminf(tb, CL));
                        t = add2(fma2(X1A, ly1.y, fma2(X2A, ly2.y, q.y)), nR0);
                        upk(t, ta, tb);
                        a0 += ex2(fminf(ta, CL)); a1 += ex2(fminf(tb, CL));
                        t = add2(fma2(X1B, ly1.x, fma2(X2B, ly2.x, q.x)), nR1);
                        upk(t, ta, tb);
                        a2 += ex2(fminf(ta, CL)); a3 += ex2(fminf(tb, CL));
                        t = add2(fma2(X1B, ly1.y, fma2(X2B, ly2.y, q.y)), nR1);
                        upk(t, ta, tb);
                        a2 += ex2(fminf(ta, CL)); a3 += ex2(fminf(tb, CL));
                    }
                }
            } else {
                for (int c = w; c < nch; c += NW) {
                    const ulonglong2* y1 = (const ulonglong2*)(Y1c + c * 16);
                    const ulonglong2* y2 = (const ulonglong2*)(Y2c + c * 16);
                    const ulonglong2* qq = (const ulonglong2*)(Qyc + c * 16);
                    #pragma unroll
                    for (int j = 0; j < 4; j++) {
                        ulonglong2 ly1 = y1[j], ly2 = y2[j], q = qq[j];
                        ull t; float ta, tb;
                        t = add2(fma2(X1A, ly1.x, fma2(X2A, ly2.x, q.x)), nR0);
                        upk(t, ta, tb);
                        a0 += ex2(ta); a1 += ex2(tb);
                        t = add2(fma2(X1A, ly1.y, fma2(X2A, ly2.y, q.y)), nR0);
                        upk(t, ta, tb);
                        a0 += ex2(ta); a1 += ex2(tb);
                        t = add2(fma2(X1B, ly1.x, fma2(X2B, ly2.x, q.x)), nR1);
                        upk(t, ta, tb);
                        a2 += ex2(ta); a3 += ex2(tb);
                        t = add2(fma2(X1B, ly1.y, fma2(X2B, ly2.y, q.y)), nR1);
                        upk(t, ta, tb);
                        a2 += ex2(ta); a3 += ex2(tb);
                    }
                }
            }
            sA[w * 64 + lane] = a0 + a1;  sA[w * 64 + lane + 32] = a2 + a3;
        }
        __syncthreads();
        if (tid < 64) {
            float A = 0.f;
            #pragma unroll
            for (int i = 0; i < NW; i++) A += sA[i * 64 + tid];
            A = fmaxf(A, 1e-30f);
            float Lse = sRf[tid] + lg2(A);
            sRf[tid] = Lse;
            QxL[tid] = -LOG2S - Lse;     // Qx-form directly (Lse already carries +xn)
        }
        __syncthreads();   // QxL visible locally; NO batch barrier needed

        // ======== iter-0 only: seed Rg via per-column max partials ========
        if (it == 0) {
            for (int u = w; u < ncp; u += NW) {
                int j1 = u * 64 + lane, j2 = j1 + 32;
                ull Y1pA = pk(Y1c[j1], Y1c[j1]), Y2pA = pk(Y2c[j1], Y2c[j1]);
                ull Y1pB = pk(Y1c[j2], Y1c[j2]), Y2pB = pk(Y2c[j2], Y2c[j2]);
                float m1v = -3e38f, m2v = -3e38f;
                const ulonglong2* x1 = (const ulonglong2*)X1L;
                const ulonglong2* x2 = (const ulonglong2*)X2L;
                const ulonglong2* qx = (const ulonglong2*)QxL;
                #pragma unroll 4
                for (int r = 0; r < 16; r++) {
                    ulonglong2 lx1 = x1[r], lx2 = x2[r], lq = qx[r];
                    ull t; float a, b2;
                    t = fma2(Y1pA, lx1.x, fma2(Y2pA, lx2.x, lq.x));
                    upk(t, a, b2); m1v = fmaxf(m1v, fmaxf(a, b2));
                    t = fma2(Y1pA, lx1.y, fma2(Y2pA, lx2.y, lq.y));
                    upk(t, a, b2); m1v = fmaxf(m1v, fmaxf(a, b2));
                    t = fma2(Y1pB, lx1.x, fma2(Y2pB, lx2.x, lq.x));
                    upk(t, a, b2); m2v = fmaxf(m2v, fmaxf(a, b2));
                    t = fma2(Y1pB, lx1.y, fma2(Y2pB, lx2.y, lq.y));
                    upk(t, a, b2); m2v = fmaxf(m2v, fmaxf(a, b2));
                }
                g_pp[(b * Pn + j1) * CPB + cb] = m1v;
                g_pp[(b * Pn + j2) * CPB + cb] = m2v;
            }
            bat_bar(b, ls);
            if (tid < 32) {
                int j = col0 + tid; float v;
                if (j < Pv) {
                    const float* pp = g_pp + (b * Pn + j) * CPB;
                    float M = -3e38f;
                    #pragma unroll
                    for (int i = 0; i < CPB; i++) M = fmaxf(M, __ldcg(pp + i));
                    v = l2bC[j] - M;                 // fake gs encoding Rg
                } else v = -1e30f;
                g_gs[b * Pn + j] = v;
            }
            bat_bar(b, ls);
            for (int i = tid; i < Pn; i += NT) {
                float q = __ldcg(&g_gs[b * Pn + i]);
                Qyc[i] = q; RgA[i] = l2bC[i] - q;    // RgA = Rg
            }
            __syncthreads();
        }

        // ================= g partials: own 64 rows x all live columns ========
        {
            for (int u = w; u < ncp; u += NW) {
                int j1 = u * 64 + lane, j2 = j1 + 32;
                ull Y1pA = pk(Y1c[j1], Y1c[j1]), Y2pA = pk(Y2c[j1], Y2c[j1]);
                ull Y1pB = pk(Y1c[j2], Y1c[j2]), Y2pB = pk(Y2c[j2], Y2c[j2]);
                float R1 = RgA[j1], R2 = RgA[j2];
                ull nR1 = pk(-R1, -R1), nR2 = pk(-R2, -R2);
                float a0 = 0.f, a1 = 0.f, b0 = 0.f, b1 = 0.f;
                const ulonglong2* x1 = (const ulonglong2*)X1L;
                const ulonglong2* x2 = (const ulonglong2*)X2L;
                const ulonglong2* qx = (const ulonglong2*)QxL;
                if (it < PH) {
                    #pragma unroll 4
                    for (int r = 0; r < 16; r++) {
                        ulonglong2 lx1 = x1[r], lx2 = x2[r], lq = qx[r];
                        ull t; float ta, tb;
                        t = add2(fma2(Y1pA, lx1.x, fma2(Y2pA, lx2.x, lq.x)), nR1);
                        upk(t, ta, tb);
                        a0 += ex2(fminf(ta, CL)); a1 += ex2(fminf(tb, CL));
                        t = add2(fma2(Y1pA, lx1.y, fma2(Y2pA, lx2.y, lq.y)), nR1);
                        upk(t, ta, tb);
                        a0 += ex2(fminf(ta, CL)); a1 += ex2(fminf(tb, CL));
                        t = add2(fma2(Y1pB, lx1.x, fma2(Y2pB, lx2.x, lq.x)), nR2);
                        upk(t, ta, tb);
                        b0 += ex2(fminf(ta, CL)); b1 += ex2(fminf(tb, CL));
                        t = add2(fma2(Y1pB, lx1.y, fma2(Y2pB, lx2.y, lq.y)), nR2);
                        upk(t, ta, tb);
                        b0 += ex2(fminf(ta, CL)); b1 += ex2(fminf(tb, CL));
                    }
                } else {
                    #pragma unroll 4
                    for (int r = 0; r < 16; r++) {
                        ulonglong2 lx1 = x1[r], lx2 = x2[r], lq = qx[r];
                        ull t; float ta, tb;
                        t = add2(fma2(Y1pA, lx1.x, fma2(Y2pA, lx2.x, lq.x)), nR1);
                        upk(t, ta, tb);
                        a0 += ex2(ta); a1 += ex2(tb);
                        t = add2(fma2(Y1pA, lx1.y, fma2(Y2pA, lx2.y, lq.y)), nR1);
                        upk(t, ta, tb);
                        a0 += ex2(ta); a1 += ex2(tb);
                        t = add2(fma2(Y1pB, lx1.x, fma2(Y2pB, lx2.x, lq.x)), nR2);
                        upk(t, ta, tb);
                        b0 += ex2(ta); b1 += ex2(tb);
                        t = add2(fma2(Y1pB, lx1.y, fma2(Y2pB, lx2.y, lq.y)), nR2);
                        upk(t, ta, tb);
                        b0 += ex2(ta); b1 += ex2(tb);
                    }
                }
                g_pp[(b * Pn + j1) * CPB + cb] = a0 + a1;
                g_pp[(b * Pn + j2) * CPB + cb] = b0 + b1;
            }
        }
        bat_bar(b, ls);
        // ---- combine for own 32 columns (fixed order -> deterministic) ----
        if (tid < 32) {
            int j = col0 + tid; float v;
            if (j < Pv) {
                const float* pp = g_pp + (b * Pn + j) * CPB;
                float A = 0.f;
                #pragma unroll
                for (int i = 0; i < CPB; i++) A += __ldcg(pp + i);
                A = fmaxf(A, 1e-30f);
                v = l2bC[j] - (RgA[j] + lg2(A));     // Qy-form gs
            } else v = -1e30f;
            g_gs[b * Pn + j] = v;
        }
        bat_bar(b, ls);
        for (int i = tid; i < Pn; i += NT) {
            float q = __ldcg(&g_gs[b * Pn + i]);
            Qyc[i] = q; RgA[i] = l2bC[i] - q;        // next iter's g reference
        }
        __syncthreads();
    }

    // ================= final transport distance =================
    {
        float q0 = QxL[lane], q1 = QxL[lane + 32];
        float xna = 0.25f * (X1a * X1a + X2a * X2a);
        float xnb = 0.25f * (X1b_ * X1b_ + X2b_ * X2b_);
        float acc = 0.f;
        for (int c = w; c < nch; c += NW) {
            const ull* y1 = (const ull*)(Y1c + c * 16);
            const ull* y2 = (const ull*)(Y2c + c * 16);
            const ull* qq = (const ull*)(Qyc + c * 16);
            #pragma unroll
            for (int j = 0; j < 8; j++) {
                ull ly1 = y1[j], ly2 = y2[j], q = qq[j];
                ull t0 = fma2(X1A, ly1, fma2(X2A, ly2, q));
                ull t1 = fma2(X1B, ly1, fma2(X2B, ly2, q));
                float qa, qb, y1a, y1b, y2a, y2b, t0a, t0b, t1a, t1b;
                upk(q, qa, qb); upk(ly1, y1a, y1b); upk(ly2, y2a, y2b);
                upk(t0, t0a, t0b); upk(t1, t1a, t1b);
                float yna2 = y1a * y1a + y2a * y2a, ynb2 = y1b * y1b + y2b * y2b;
                acc = fmaf(ex2(fminf(t0a + q0, CL)), qa + yna2 + xna - t0a, acc);
                acc = fmaf(ex2(fminf(t0b + q0, CL)), qb + ynb2 + xna - t0b, acc);
                acc = fmaf(ex2(fminf(t1a + q1, CL)), qa + yna2 + xnb - t1a, acc);
                acc = fmaf(ex2(fminf(t1b + q1, CL)), qb + ynb2 + xnb - t1b, acc);
            }
        }
        acc = warp_sum(acc);
        if (lane == 0) sred[w] = acc;
    }
    __syncthreads();
    if (tid == 0) {
        float s = 0.f;
        #pragma unroll
        for (int i = 0; i < NW; i++) s += sred[i];
        g_part[blockIdx.x] = s;
    }

    // ---- grid-wide deterministic reduce ----
    __threadfence();
    __syncthreads();
    if (blockIdx.x == 0) {
        if (tid == 0) {
            atomicAdd(&g_gcnt, 1u);
            while (*((volatile unsigned*)&g_gcnt) < (unsigned)GRID) { }
            __threadfence();
        }
        __syncthreads();
        sA[tid] = __ldcg(&g_part[tid]);
        __syncthreads();
        #pragma unroll
        for (int o = 128; o; o >>= 1) {
            if (tid < o) sA[tid] += sA[tid + o];
            __syncthreads();
        }
        if (tid == 0) {
            out[0] = sA[0] * (1.f / (IL2 * (float)Bn));
            g_gcnt = 0;
        }
    } else {
        if (tid == 0) atomicAdd(&g_gcnt, 1u);
    }
}

extern "C" void kernel_launch(void* const* d_in, const int* in_sizes, int n_in,
                              void* d_out, int out_size) {
    const float* pred   = (const float*)d_in[0];
    const int*   labels = (const int*)d_in[1];
    const float* pos    = (const float*)d_in[2];
    float*       out    = (float*)d_out;

    sinkhorn_kernel<<<GRID, NT>>>(pred, labels, pos, out);
}